// round 14
// baseline (speedup 1.0000x reference)
#include <cuda_runtime.h>
#include <cuda_bf16.h>
#include <cstdint>

// ============================================================================
// IntegerCifar10Net R14: bf16 HMMA convs. L2/L3/L4: M32xN32 warp tiles with
// register double-buffered fragment pipeline (ldsm latency hidden), occ 2.
// L5/L6: M32xN64 unpipelined (occ 2). L2/L4 fuse 2x2 maxpool; L6 fuses
// pool + int8 packing for FC1. Exact integer math throughout.
// ============================================================================

__device__ __forceinline__ int qlev(float w) {
    w = fminf(fmaxf(w, -1.0f), 1.0f);
    return (int)rintf(w * 7.0f);
}
__device__ __forceinline__ unsigned pack_bf16x2(float lo, float hi) {
    unsigned r;
    asm("cvt.rn.bf16x2.f32 %0, %1, %2;" : "=r"(r) : "f"(hi), "f"(lo));
    return r;
}
__device__ __forceinline__ unsigned smem_u32(const void* p) {
    return (unsigned)__cvta_generic_to_shared(p);
}
__device__ __forceinline__ void cp16(unsigned dst, const void* src, int szvalid) {
    asm volatile("cp.async.cg.shared.global [%0], [%1], 16, %2;"
                 :: "r"(dst), "l"(src), "r"(szvalid) : "memory");
}
__device__ __forceinline__ void cp_commit_wait() {
    asm volatile("cp.async.commit_group;" ::: "memory");
    asm volatile("cp.async.wait_group 0;" ::: "memory");
}
__device__ __forceinline__ void ldsm4(unsigned* r, unsigned addr) {
    asm volatile("ldmatrix.sync.aligned.m8n8.x4.shared.b16 {%0,%1,%2,%3}, [%4];"
                 : "=r"(r[0]), "=r"(r[1]), "=r"(r[2]), "=r"(r[3]) : "r"(addr));
}

// ---------------- scratch ----------------
__device__ __nv_bfloat16 g_bufA[512 * 32 * 32 * 64];
__device__ __nv_bfloat16 g_bufB[512 * 32 * 32 * 64];
__device__ float         g_qw1[64 * 3 * 9];
__device__ __nv_bfloat16 g_wb2[9 * 1 * 64 * 64];
__device__ __nv_bfloat16 g_wb3[9 * 1 * 128 * 64];
__device__ __nv_bfloat16 g_wb4[9 * 2 * 128 * 64];
__device__ __nv_bfloat16 g_wb5[9 * 2 * 256 * 64];
__device__ __nv_bfloat16 g_wb6[9 * 4 * 256 * 64];
__device__ int           g_wf1[512 * 1024];
__device__ signed char   g_wf2[10 * 512];
__device__ unsigned char g_fc1[512 * 512];

// ---------------- fused weight prep ----------------
__device__ __forceinline__ void pack_one_convw(const float* w, __nv_bfloat16* out,
                                               int COUT, int CIN, int idx) {
    int NCH = CIN / 64;
    int j = idx % 64;
    int t = idx / 64;
    int oc = t % COUT; t /= COUT;
    int ch = t % NCH;
    int kpos = t / NCH;
    out[idx] = __float2bfloat16((float)qlev(w[(oc * CIN + ch * 64 + j) * 9 + kpos]));
}

__global__ void prep_all(const float* w1, const float* w2, const float* w3,
                         const float* w4, const float* w5, const float* w6,
                         const float* wf1, const float* wf2,
                         float* qw1, __nv_bfloat16* o2, __nv_bfloat16* o3,
                         __nv_bfloat16* o4, __nv_bfloat16* o5, __nv_bfloat16* o6,
                         int* of1, signed char* of2) {
    int idx = blockIdx.x * blockDim.x + threadIdx.x;
    const int S0 = 1728, S1 = 36864, S2 = 73728, S3 = 147456,
              S4 = 294912, S5 = 589824, S6 = 524288, S7 = 5120;
    if (idx < S0) { qw1[idx] = (float)qlev(w1[idx]) / 7.0f; return; }
    idx -= S0;
    if (idx < S1) { pack_one_convw(w2, o2, 64, 64, idx); return; }
    idx -= S1;
    if (idx < S2) { pack_one_convw(w3, o3, 128, 64, idx); return; }
    idx -= S2;
    if (idx < S3) { pack_one_convw(w4, o4, 128, 128, idx); return; }
    idx -= S3;
    if (idx < S4) { pack_one_convw(w5, o5, 256, 128, idx); return; }
    idx -= S4;
    if (idx < S5) { pack_one_convw(w6, o6, 256, 256, idx); return; }
    idx -= S5;
    if (idx < S6) {
        int wi = idx % 1024, o = idx / 1024;
        int px = wi / 64, c4 = wi % 64;
        unsigned word = 0;
#pragma unroll
        for (int l = 0; l < 4; l++) {
            int k = (4 * c4 + l) * 16 + px;
            word |= (unsigned)(qlev(wf1[o * 4096 + k]) & 0xFF) << (8 * l);
        }
        of1[idx] = (int)word;
        return;
    }
    idx -= S6;
    if (idx < S7) of2[idx] = (signed char)qlev(wf2[idx]);
}

// ---------------- conv1: fp32 NCHW -> bf16 NHWC levels ----------------
__global__ void __launch_bounds__(1024)
conv1_kernel(const float* __restrict__ x, const float* __restrict__ qw,
             const float* __restrict__ g, const float* __restrict__ b,
             __nv_bfloat16* __restrict__ out) {
    __shared__ float s_in[3][34][34];
    __shared__ float s_w[16][27];
    const int tid = threadIdx.x;
    const int oy = tid / 32, ox = tid % 32;
    const int n = blockIdx.y;
    const int oc0 = blockIdx.x * 16;
    for (int i = tid; i < 3 * 34 * 34; i += 1024) {
        int t = i;
        int xx = t % 34; t /= 34;
        int yy = t % 34; t /= 34;
        int c = t;
        int yi = yy - 1, xi = xx - 1;
        float v = 0.0f;
        if ((unsigned)yi < 32u && (unsigned)xi < 32u)
            v = x[((n * 3 + c) * 32 + yi) * 32 + xi];
        s_in[c][yy][xx] = v;
    }
    for (int i = tid; i < 16 * 27; i += 1024)
        s_w[i / 27][i % 27] = qw[(oc0 + i / 27) * 27 + i % 27];
    __syncthreads();
    float acc[16];
#pragma unroll
    for (int o = 0; o < 16; o++) acc[o] = 0.0f;
#pragma unroll
    for (int c = 0; c < 3; c++) {
        float wv[9];
#pragma unroll
        for (int ky = 0; ky < 3; ky++)
#pragma unroll
            for (int kx = 0; kx < 3; kx++)
                wv[ky * 3 + kx] = s_in[c][oy + ky][ox + kx];
#pragma unroll
        for (int o = 0; o < 16; o++) {
            float a = acc[o];
#pragma unroll
            for (int k = 0; k < 9; k++) a = fmaf(wv[k], s_w[o][c * 9 + k], a);
            acc[o] = a;
        }
    }
    unsigned* ob = (unsigned*)(out + ((size_t)(n * 1024) + oy * 32 + ox) * 64 + oc0);
#pragma unroll
    for (int j = 0; j < 8; j++) {
        float lv[2];
#pragma unroll
        for (int l = 0; l < 2; l++) {
            int o = j * 2 + l;
            float p = acc[o] * g[oc0 + o] + b[oc0 + o];
            p = fminf(fmaxf(p, -1.0f), 1.0f);
            lv[l] = fmaxf(rintf(p * 7.0f), 0.0f);
        }
        ob[j] = pack_bf16x2(lv[0], lv[1]);
    }
}

// ---------------- bf16 HMMA conv ----------------
__device__ __forceinline__ void mma_bf16(float* d, const unsigned* a, unsigned b0, unsigned b1) {
    asm volatile(
        "mma.sync.aligned.m16n8k16.row.col.f32.bf16.bf16.f32 "
        "{%0,%1,%2,%3},{%4,%5,%6,%7},{%8,%9},{%0,%1,%2,%3};"
        : "+f"(d[0]), "+f"(d[1]), "+f"(d[2]), "+f"(d[3])
        : "r"(a[0]), "r"(a[1]), "r"(a[2]), "r"(a[3]), "r"(b0), "r"(b1));
}

// act [n][H][W][CIN] bf16 ; weight [kpos][ch][oc][64] bf16
// Warp tile M=32 px, N=TOC oc. POOL: 0=none, 1=pooled bf16 out (TY=TX=16,NB=1),
// 2=pooled packed-int8 out for FC1 (TY=TX=8, NB=4, TOC=64).
// PIPE=1 (requires TOC=32): register double-buffered fragment pipeline.
template <int H, int W, int TY, int TX, int NB, int CIN, int COUT, int POOL,
          int TOC, int MINB, int PIPE>
__global__ void __launch_bounds__(256, MINB)
conv_hmma(const __nv_bfloat16* __restrict__ in, const __nv_bfloat16* __restrict__ wq,
          const float* __restrict__ g, const float* __restrict__ bb,
          __nv_bfloat16* __restrict__ out) {
    constexpr int NCH = CIN / 64;
    constexpr int KCP = 144;                 // 128B chunk + 16B pad
    constexpr int PXT = TY * TX;
    constexpr int SIN_PIX = NB * (TY + 2) * (TX + 2);
    constexpr int NI = TOC / 8;              // acc col-tiles
    constexpr int NP = TOC / 16;             // B ldsm per k-step

    extern __shared__ char smem[];
    char* s_in = smem;                       // SIN_PIX * KCP
    char* s_w  = smem + SIN_PIX * KCP;       // 5 * TOC * KCP (max group)

    const int tid  = threadIdx.x;
    const int warp = tid >> 5, lane = tid & 31;
    const int oc0  = blockIdx.x * TOC;
    const int ty0  = (blockIdx.y / (W / TX)) * TY;
    const int tx0  = (blockIdx.y % (W / TX)) * TX;
    const int n0   = blockIdx.z * NB;
    const char* inb = (const char*)in;
    const char* wqb = (const char*)wq;

    float acc[2][NI][4];
#pragma unroll
    for (int mi = 0; mi < 2; mi++)
#pragma unroll
        for (int ni = 0; ni < NI; ni++)
#pragma unroll
            for (int j = 0; j < 4; j++) acc[mi][ni][j] = 0.0f;

    unsigned Abase[2];
#pragma unroll
    for (int mi = 0; mi < 2; mi++) {
        int row_local = ((lane >> 3) & 1) * 8 + (lane & 7);
        int p = warp * 32 + mi * 16 + row_local;
        int nn = p / PXT, rem = p % PXT;
        int py = rem / TX, px = rem % TX;
        Abase[mi] = smem_u32(s_in) + ((nn * (TY + 2) + py) * (TX + 2) + px) * KCP
                    + (lane >> 4) * 16;
    }
    const unsigned Bbase = smem_u32(s_w) + ((lane & 7) + (lane >> 4) * 8) * KCP
                           + ((lane >> 3) & 1) * 16;

    for (int ch = 0; ch < NCH; ch++) {
#pragma unroll
        for (int grp = 0; grp < 2; grp++) {
            const int k0 = grp ? 5 : 0;
            const int kN = grp ? 4 : 5;
            if (grp == 0) {
                for (int u = tid; u < SIN_PIX * 8; u += 256) {
                    int j   = u & 7;
                    int pix = u >> 3;
                    int xx  = pix % (TX + 2);
                    int yy  = (pix / (TX + 2)) % (TY + 2);
                    int nn  = pix / ((TX + 2) * (TY + 2));
                    int gy = ty0 + yy - 1, gx = tx0 + xx - 1;
                    bool ok = (unsigned)gy < (unsigned)H && (unsigned)gx < (unsigned)W;
                    const char* src = ok
                        ? inb + ((((size_t)(n0 + nn) * H + gy) * W + gx) * CIN + ch * 64 + j * 8) * 2
                        : inb;
                    cp16(smem_u32(s_in + pix * KCP + j * 16), src, ok ? 16 : 0);
                }
            }
            for (int u = tid; u < kN * TOC * 8; u += 256) {
                int j   = u & 7;
                int r   = (u >> 3) % TOC;
                int kl  = u / (TOC * 8);
                const char* src = wqb +
                    (((size_t)((k0 + kl) * NCH + ch) * COUT + oc0 + r) * 64 + j * 8) * 2;
                cp16(smem_u32(s_w + (kl * TOC + r) * KCP + j * 16), src, 16);
            }
            cp_commit_wait();
            __syncthreads();

            if (PIPE) {
                // register double-buffered pipeline over flattened (kl,ks)
                unsigned fa0[2][4], fa1[2][4], fb[2][8];
                {
                    const int off = ((k0 / 3) * (TX + 2) + (k0 % 3)) * KCP;
                    ldsm4(fa0[0], Abase[0] + off);
                    ldsm4(fa1[0], Abase[1] + off);
                    ldsm4(fb[0],     Bbase);
                    ldsm4(fb[0] + 4, Bbase + 16 * KCP);
                }
                const int NITER = kN * 4;
#pragma unroll
                for (int it = 0; it < 5 * 4; it++) {
                    if (it >= NITER) break;
                    const int cur = it & 1, nxt = cur ^ 1;
                    const int n1 = it + 1;
                    if (n1 < NITER) {
                        const int kl = n1 >> 2, ks = n1 & 3;
                        const int kpos = k0 + kl;
                        const int off = ((kpos / 3) * (TX + 2) + (kpos % 3)) * KCP + ks * 32;
                        ldsm4(fa0[nxt], Abase[0] + off);
                        ldsm4(fa1[nxt], Abase[1] + off);
                        ldsm4(fb[nxt],     Bbase + (kl * TOC) * KCP + ks * 32);
                        ldsm4(fb[nxt] + 4, Bbase + (kl * TOC + 16) * KCP + ks * 32);
                    }
#pragma unroll
                    for (int np = 0; np < 2; np++) {
                        mma_bf16(acc[0][2 * np],     fa0[cur], fb[cur][4 * np],     fb[cur][4 * np + 1]);
                        mma_bf16(acc[0][2 * np + 1], fa0[cur], fb[cur][4 * np + 2], fb[cur][4 * np + 3]);
                        mma_bf16(acc[1][2 * np],     fa1[cur], fb[cur][4 * np],     fb[cur][4 * np + 1]);
                        mma_bf16(acc[1][2 * np + 1], fa1[cur], fb[cur][4 * np + 2], fb[cur][4 * np + 3]);
                    }
                }
            } else {
#pragma unroll
                for (int kl = 0; kl < (grp ? 4 : 5); kl++) {
                    const int kpos = k0 + kl;
                    const int off0 = ((kpos / 3) * (TX + 2) + (kpos % 3)) * KCP;
#pragma unroll
                    for (int ks = 0; ks < 4; ks++) {
                        const int off = off0 + ks * 32;
                        unsigned a0[4], a1[4];
                        ldsm4(a0, Abase[0] + off);
                        ldsm4(a1, Abase[1] + off);
#pragma unroll
                        for (int np = 0; np < NP; np++) {
                            unsigned b[4];
                            ldsm4(b, Bbase + (kl * TOC + np * 16) * KCP + ks * 32);
                            mma_bf16(acc[0][2 * np],     a0, b[0], b[1]);
                            mma_bf16(acc[0][2 * np + 1], a0, b[2], b[3]);
                            mma_bf16(acc[1][2 * np],     a1, b[0], b[1]);
                            mma_bf16(acc[1][2 * np + 1], a1, b[2], b[3]);
                        }
                    }
                }
            }
            __syncthreads();
        }
    }

    if (POOL == 1) {
        const int q = lane >> 2;
#pragma unroll
        for (int half = 0; half < 2; half++) {
            const int px = half * 8 + q;
#pragma unroll
            for (int ni = 0; ni < NI; ni++) {
                int col = ni * 8 + (lane & 3) * 2;
                float m[2];
#pragma unroll
                for (int l = 0; l < 2; l++) {
                    float lv2[2];
#pragma unroll
                    for (int mi = 0; mi < 2; mi++) {
                        float y = acc[mi][ni][half * 2 + l] / 49.0f;
                        float p = y * g[oc0 + col + l] + bb[oc0 + col + l];
                        p = fminf(fmaxf(p, -1.0f), 1.0f);
                        lv2[mi] = fmaxf(rintf(p * 7.0f), 0.0f);
                    }
                    m[l] = fmaxf(lv2[0], lv2[1]);
                    m[l] = fmaxf(m[l], __shfl_xor_sync(0xFFFFFFFFu, m[l], 4));
                }
                if (!(q & 1)) {
                    int oy = ty0 / 2 + warp;
                    int ox = tx0 / 2 + px / 2;
                    size_t ob = (((size_t)n0 * (H / 2) + oy) * (W / 2) + ox) * COUT + oc0 + col;
                    *(unsigned*)((char*)out + ob * 2) = pack_bf16x2(m[0], m[1]);
                }
            }
        }
    } else if (POOL == 2) {
        const int q = lane >> 2;
#pragma unroll
        for (int mi = 0; mi < 2; mi++) {
            int rbase = warp * 32 + mi * 16;
            int nn = rbase / PXT;
            int py = (rbase % PXT) / TX;
            int oy = py >> 1;
#pragma unroll
            for (int ni = 0; ni < NI; ni++) {
                int col = ni * 8 + (lane & 3) * 2;
                float m[2];
#pragma unroll
                for (int l = 0; l < 2; l++) {
                    float lv2[2];
#pragma unroll
                    for (int half = 0; half < 2; half++) {
                        float y = acc[mi][ni][half * 2 + l] / 49.0f;
                        float p = y * g[oc0 + col + l] + bb[oc0 + col + l];
                        p = fminf(fmaxf(p, -1.0f), 1.0f);
                        lv2[half] = fmaxf(rintf(p * 7.0f), 0.0f);
                    }
                    m[l] = fmaxf(lv2[0], lv2[1]);
                    m[l] = fmaxf(m[l], __shfl_xor_sync(0xFFFFFFFFu, m[l], 4));
                }
                unsigned hw = (unsigned)(int)m[0] | ((unsigned)(int)m[1] << 8);
                unsigned other = __shfl_xor_sync(0xFFFFFFFFu, hw, 1);
                if ((lane & 5) == 0) {
                    int c4 = (oc0 >> 2) + 2 * ni + ((lane & 3) >> 1);
                    int ox = q >> 1;
                    int pxi = oy * 4 + ox;
                    ((unsigned*)out)[(size_t)(n0 + nn) * 1024 + pxi * 64 + c4] =
                        hw | (other << 16);
                }
            }
        }
    } else {
#pragma unroll
        for (int mi = 0; mi < 2; mi++) {
#pragma unroll
            for (int half = 0; half < 2; half++) {
                int row = warp * 32 + mi * 16 + (lane >> 2) + half * 8;
                int nn = row / PXT, rem = row % PXT;
                int py = rem / TX, px = rem % TX;
                size_t ob = (((size_t)(n0 + nn) * H + ty0 + py) * W + tx0 + px) * COUT + oc0;
#pragma unroll
                for (int ni = 0; ni < NI; ni++) {
                    int col = ni * 8 + (lane & 3) * 2;
                    float lv[2];
#pragma unroll
                    for (int l = 0; l < 2; l++) {
                        float y = acc[mi][ni][half * 2 + l] / 49.0f;
                        float p = y * g[oc0 + col + l] + bb[oc0 + col + l];
                        p = fminf(fmaxf(p, -1.0f), 1.0f);
                        lv[l] = fmaxf(rintf(p * 7.0f), 0.0f);
                    }
                    *(unsigned*)((char*)out + (ob + col) * 2) = pack_bf16x2(lv[0], lv[1]);
                }
            }
        }
    }
}

// ---------------- FC ----------------
__global__ void fc1_kernel(const int* __restrict__ h, const int* __restrict__ w,
                           const float* __restrict__ g, const float* __restrict__ b,
                           unsigned char* __restrict__ out) {
    __shared__ int sa[16][17];
    __shared__ int sw[16][17];
    const int tx = threadIdx.x, ty = threadIdx.y;
    const int n = blockIdx.y * 16 + ty;
    const int o = blockIdx.x * 16 + tx;
    int acc = 0;
    for (int m0 = 0; m0 < 1024; m0 += 16) {
        sa[ty][tx] = h[(blockIdx.y * 16 + ty) * 1024 + m0 + tx];
        sw[ty][tx] = w[(blockIdx.x * 16 + ty) * 1024 + m0 + tx];
        __syncthreads();
#pragma unroll
        for (int mm = 0; mm < 16; mm++) acc = __dp4a(sa[ty][mm], sw[tx][mm], acc);
        __syncthreads();
    }
    float y = (float)acc / 49.0f;
    float p = y * g[o] + b[o];
    p = fminf(fmaxf(p, -1.0f), 1.0f);
    int lev = max((int)rintf(p * 7.0f), 0);
    out[n * 512 + o] = (unsigned char)lev;
}
__global__ void fc2_kernel(const unsigned char* __restrict__ h,
                           const signed char* __restrict__ w,
                           const float* __restrict__ g, const float* __restrict__ b,
                           float* __restrict__ out) {
    const int n = blockIdx.x;
    const int lane = threadIdx.x;
    for (int o = 0; o < 10; o++) {
        int acc = 0;
        for (int k = lane; k < 512; k += 32)
            acc += (int)h[n * 512 + k] * (int)w[o * 512 + k];
#pragma unroll
        for (int off = 16; off > 0; off >>= 1)
            acc += __shfl_xor_sync(0xFFFFFFFFu, acc, off);
        if (lane == 0) {
            float y = (float)acc / 49.0f;
            float p = y * g[o] + b[o];
            p = fminf(fmaxf(p, -1.0f), 1.0f);
            out[n * 10 + o] = (float)((int)rintf(p * 7.0f)) / 7.0f;
        }
    }
}

// ---------------- launch ----------------
extern "C" void kernel_launch(void* const* d_in, const int* in_sizes, int n_in,
                              void* d_out, int out_size) {
    const float* x = (const float*)d_in[0];
    const float *w1 = (const float*)d_in[1], *g1 = (const float*)d_in[2], *b1 = (const float*)d_in[3];
    const float *w2 = (const float*)d_in[4], *g2 = (const float*)d_in[5], *b2 = (const float*)d_in[6];
    const float *w3 = (const float*)d_in[7], *g3 = (const float*)d_in[8], *b3 = (const float*)d_in[9];
    const float *w4 = (const float*)d_in[10], *g4 = (const float*)d_in[11], *b4 = (const float*)d_in[12];
    const float *w5 = (const float*)d_in[13], *g5 = (const float*)d_in[14], *b5 = (const float*)d_in[15];
    const float *w6 = (const float*)d_in[16], *g6 = (const float*)d_in[17], *b6 = (const float*)d_in[18];
    const float *wf1 = (const float*)d_in[19], *gf1 = (const float*)d_in[20], *bf1 = (const float*)d_in[21];
    const float *wf2 = (const float*)d_in[22], *gf2 = (const float*)d_in[23], *bf2 = (const float*)d_in[24];

    void *bufA, *bufB, *qw1, *w2p, *w3p, *w4p, *w5p, *w6p, *wf1p, *wf2p, *fc1o;
    cudaGetSymbolAddress(&bufA, g_bufA);
    cudaGetSymbolAddress(&bufB, g_bufB);
    cudaGetSymbolAddress(&qw1, g_qw1);
    cudaGetSymbolAddress(&w2p, g_wb2);
    cudaGetSymbolAddress(&w3p, g_wb3);
    cudaGetSymbolAddress(&w4p, g_wb4);
    cudaGetSymbolAddress(&w5p, g_wb5);
    cudaGetSymbolAddress(&w6p, g_wb6);
    cudaGetSymbolAddress(&wf1p, g_wf1);
    cudaGetSymbolAddress(&wf2p, g_wf2);
    cudaGetSymbolAddress(&fc1o, g_fc1);

    auto k2 = conv_hmma<32, 32, 16, 16, 1, 64, 64, 1, 32, 2, 1>;     // pool -> 16x16
    auto k3 = conv_hmma<16, 16, 16, 16, 1, 64, 128, 0, 32, 2, 1>;
    auto k4 = conv_hmma<16, 16, 16, 16, 1, 128, 128, 1, 32, 2, 1>;   // pool -> 8x8
    auto k5 = conv_hmma<8, 8, 8, 8, 4, 128, 256, 0, 64, 2, 0>;
    auto k6 = conv_hmma<8, 8, 8, 8, 4, 256, 256, 2, 64, 2, 0>;       // pool+int8 pack
    const int sm32 = (1 * 18 * 18) * 144 + 5 * 32 * 144;   // 69696
    const int sm64 = (4 * 10 * 10) * 144 + 5 * 64 * 144;   // 103680
    cudaFuncSetAttribute(k2, cudaFuncAttributeMaxDynamicSharedMemorySize, sm32);
    cudaFuncSetAttribute(k3, cudaFuncAttributeMaxDynamicSharedMemorySize, sm32);
    cudaFuncSetAttribute(k4, cudaFuncAttributeMaxDynamicSharedMemorySize, sm32);
    cudaFuncSetAttribute(k5, cudaFuncAttributeMaxDynamicSharedMemorySize, sm64);
    cudaFuncSetAttribute(k6, cudaFuncAttributeMaxDynamicSharedMemorySize, sm64);

    prep_all<<<(1673920 + 255) / 256, 256>>>(
        w1, w2, w3, w4, w5, w6, wf1, wf2,
        (float*)qw1, (__nv_bfloat16*)w2p, (__nv_bfloat16*)w3p, (__nv_bfloat16*)w4p,
        (__nv_bfloat16*)w5p, (__nv_bfloat16*)w6p, (int*)wf1p, (signed char*)wf2p);

    conv1_kernel<<<dim3(4, 512), 1024>>>(x, (const float*)qw1, g1, b1, (__nv_bfloat16*)bufA);

    // L2+pool: 64->64 @32 -> 16x16, A->B
    k2<<<dim3(2, 4, 512), 256, sm32>>>((const __nv_bfloat16*)bufA, (const __nv_bfloat16*)w2p,
                                       g2, b2, (__nv_bfloat16*)bufB);
    // L3: 64->128 @16, B->A
    k3<<<dim3(4, 1, 512), 256, sm32>>>((const __nv_bfloat16*)bufB, (const __nv_bfloat16*)w3p,
                                       g3, b3, (__nv_bfloat16*)bufA);
    // L4+pool: 128->128 @16 -> 8x8, A->B
    k4<<<dim3(4, 1, 512), 256, sm32>>>((const __nv_bfloat16*)bufA, (const __nv_bfloat16*)w4p,
                                       g4, b4, (__nv_bfloat16*)bufB);
    // L5: 128->256 @8, B->A
    k5<<<dim3(4, 1, 128), 256, sm64>>>((const __nv_bfloat16*)bufB, (const __nv_bfloat16*)w5p,
                                       g5, b5, (__nv_bfloat16*)bufA);
    // L6+pool+pack: 256->256 @8 -> 4x4 packed int8, A->B
    k6<<<dim3(4, 1, 128), 256, sm64>>>((const __nv_bfloat16*)bufA, (const __nv_bfloat16*)w6p,
                                       g6, b6, (__nv_bfloat16*)bufB);

    fc1_kernel<<<dim3(32, 32), dim3(16, 16)>>>((const int*)bufB, (const int*)wf1p, gf1, bf1,
                                               (unsigned char*)fc1o);
    fc2_kernel<<<512, 32>>>((const unsigned char*)fc1o, (const signed char*)wf2p, gf2, bf2,
                            (float*)d_out);
}

// round 15
// speedup vs baseline: 1.0790x; 1.0790x over previous
#include <cuda_runtime.h>
#include <cuda_bf16.h>
#include <cstdint>

// ============================================================================
// IntegerCifar10Net R15: R13 champion + L5/L6 moved to occupancy-3
// (TOC=32, 3-tap weight groups). Exact integer arithmetic throughout.
// ============================================================================

__device__ __forceinline__ int qlev(float w) {
    w = fminf(fmaxf(w, -1.0f), 1.0f);
    return (int)rintf(w * 7.0f);
}
__device__ __forceinline__ unsigned pack_bf16x2(float lo, float hi) {
    unsigned r;
    asm("cvt.rn.bf16x2.f32 %0, %1, %2;" : "=r"(r) : "f"(hi), "f"(lo));
    return r;
}
__device__ __forceinline__ unsigned smem_u32(const void* p) {
    return (unsigned)__cvta_generic_to_shared(p);
}
__device__ __forceinline__ void cp16(unsigned dst, const void* src, int szvalid) {
    asm volatile("cp.async.cg.shared.global [%0], [%1], 16, %2;"
                 :: "r"(dst), "l"(src), "r"(szvalid) : "memory");
}
__device__ __forceinline__ void cp_commit_wait() {
    asm volatile("cp.async.commit_group;" ::: "memory");
    asm volatile("cp.async.wait_group 0;" ::: "memory");
}
__device__ __forceinline__ void ldsm4(unsigned* r, unsigned addr) {
    asm volatile("ldmatrix.sync.aligned.m8n8.x4.shared.b16 {%0,%1,%2,%3}, [%4];"
                 : "=r"(r[0]), "=r"(r[1]), "=r"(r[2]), "=r"(r[3]) : "r"(addr));
}

// ---------------- scratch ----------------
__device__ __nv_bfloat16 g_bufA[512 * 32 * 32 * 64];
__device__ __nv_bfloat16 g_bufB[512 * 32 * 32 * 64];
__device__ float         g_qw1[64 * 3 * 9];
__device__ __nv_bfloat16 g_wb2[9 * 1 * 64 * 64];
__device__ __nv_bfloat16 g_wb3[9 * 1 * 128 * 64];
__device__ __nv_bfloat16 g_wb4[9 * 2 * 128 * 64];
__device__ __nv_bfloat16 g_wb5[9 * 2 * 256 * 64];
__device__ __nv_bfloat16 g_wb6[9 * 4 * 256 * 64];
__device__ int           g_wf1[512 * 1024];
__device__ signed char   g_wf2[10 * 512];
__device__ unsigned char g_fc1[512 * 512];

// ---------------- fused weight prep ----------------
__device__ __forceinline__ void pack_one_convw(const float* w, __nv_bfloat16* out,
                                               int COUT, int CIN, int idx) {
    int NCH = CIN / 64;
    int j = idx % 64;
    int t = idx / 64;
    int oc = t % COUT; t /= COUT;
    int ch = t % NCH;
    int kpos = t / NCH;
    out[idx] = __float2bfloat16((float)qlev(w[(oc * CIN + ch * 64 + j) * 9 + kpos]));
}

__global__ void prep_all(const float* w1, const float* w2, const float* w3,
                         const float* w4, const float* w5, const float* w6,
                         const float* wf1, const float* wf2,
                         float* qw1, __nv_bfloat16* o2, __nv_bfloat16* o3,
                         __nv_bfloat16* o4, __nv_bfloat16* o5, __nv_bfloat16* o6,
                         int* of1, signed char* of2) {
    int idx = blockIdx.x * blockDim.x + threadIdx.x;
    const int S0 = 1728, S1 = 36864, S2 = 73728, S3 = 147456,
              S4 = 294912, S5 = 589824, S6 = 524288, S7 = 5120;
    if (idx < S0) { qw1[idx] = (float)qlev(w1[idx]) / 7.0f; return; }
    idx -= S0;
    if (idx < S1) { pack_one_convw(w2, o2, 64, 64, idx); return; }
    idx -= S1;
    if (idx < S2) { pack_one_convw(w3, o3, 128, 64, idx); return; }
    idx -= S2;
    if (idx < S3) { pack_one_convw(w4, o4, 128, 128, idx); return; }
    idx -= S3;
    if (idx < S4) { pack_one_convw(w5, o5, 256, 128, idx); return; }
    idx -= S4;
    if (idx < S5) { pack_one_convw(w6, o6, 256, 256, idx); return; }
    idx -= S5;
    if (idx < S6) {
        int wi = idx % 1024, o = idx / 1024;
        int px = wi / 64, c4 = wi % 64;
        unsigned word = 0;
#pragma unroll
        for (int l = 0; l < 4; l++) {
            int k = (4 * c4 + l) * 16 + px;
            word |= (unsigned)(qlev(wf1[o * 4096 + k]) & 0xFF) << (8 * l);
        }
        of1[idx] = (int)word;
        return;
    }
    idx -= S6;
    if (idx < S7) of2[idx] = (signed char)qlev(wf2[idx]);
}

// ---------------- conv1: fp32 NCHW -> bf16 NHWC levels ----------------
__global__ void __launch_bounds__(1024)
conv1_kernel(const float* __restrict__ x, const float* __restrict__ qw,
             const float* __restrict__ g, const float* __restrict__ b,
             __nv_bfloat16* __restrict__ out) {
    __shared__ float s_in[3][34][34];
    __shared__ float s_w[16][27];
    const int tid = threadIdx.x;
    const int oy = tid / 32, ox = tid % 32;
    const int n = blockIdx.y;
    const int oc0 = blockIdx.x * 16;
    for (int i = tid; i < 3 * 34 * 34; i += 1024) {
        int t = i;
        int xx = t % 34; t /= 34;
        int yy = t % 34; t /= 34;
        int c = t;
        int yi = yy - 1, xi = xx - 1;
        float v = 0.0f;
        if ((unsigned)yi < 32u && (unsigned)xi < 32u)
            v = x[((n * 3 + c) * 32 + yi) * 32 + xi];
        s_in[c][yy][xx] = v;
    }
    for (int i = tid; i < 16 * 27; i += 1024)
        s_w[i / 27][i % 27] = qw[(oc0 + i / 27) * 27 + i % 27];
    __syncthreads();
    float acc[16];
#pragma unroll
    for (int o = 0; o < 16; o++) acc[o] = 0.0f;
#pragma unroll
    for (int c = 0; c < 3; c++) {
        float wv[9];
#pragma unroll
        for (int ky = 0; ky < 3; ky++)
#pragma unroll
            for (int kx = 0; kx < 3; kx++)
                wv[ky * 3 + kx] = s_in[c][oy + ky][ox + kx];
#pragma unroll
        for (int o = 0; o < 16; o++) {
            float a = acc[o];
#pragma unroll
            for (int k = 0; k < 9; k++) a = fmaf(wv[k], s_w[o][c * 9 + k], a);
            acc[o] = a;
        }
    }
    unsigned* ob = (unsigned*)(out + ((size_t)(n * 1024) + oy * 32 + ox) * 64 + oc0);
#pragma unroll
    for (int j = 0; j < 8; j++) {
        float lv[2];
#pragma unroll
        for (int l = 0; l < 2; l++) {
            int o = j * 2 + l;
            float p = acc[o] * g[oc0 + o] + b[oc0 + o];
            p = fminf(fmaxf(p, -1.0f), 1.0f);
            lv[l] = fmaxf(rintf(p * 7.0f), 0.0f);
        }
        ob[j] = pack_bf16x2(lv[0], lv[1]);
    }
}

// ---------------- bf16 HMMA conv ----------------
__device__ __forceinline__ void mma_bf16(float* d, const unsigned* a, unsigned b0, unsigned b1) {
    asm volatile(
        "mma.sync.aligned.m16n8k16.row.col.f32.bf16.bf16.f32 "
        "{%0,%1,%2,%3},{%4,%5,%6,%7},{%8,%9},{%0,%1,%2,%3};"
        : "+f"(d[0]), "+f"(d[1]), "+f"(d[2]), "+f"(d[3])
        : "r"(a[0]), "r"(a[1]), "r"(a[2]), "r"(a[3]), "r"(b0), "r"(b1));
}

// act [n][H][W][CIN] bf16 ; weight [kpos][ch][oc][64] bf16
// Warp tile M=32 px, N=TOC oc. POOL: 0=none, 1=pooled bf16 out (TY=TX=16,NB=1),
// 2=pooled packed-int8 out for FC1 (TY=TX=8, NB=4, TOC arbitrary).
// WG = taps per weight-stage group (5 -> groups {5,4}; 3 -> {3,3,3}).
template <int H, int W, int TY, int TX, int NB, int CIN, int COUT, int POOL,
          int TOC, int MINB, int WG>
__global__ void __launch_bounds__(256, MINB)
conv_hmma(const __nv_bfloat16* __restrict__ in, const __nv_bfloat16* __restrict__ wq,
          const float* __restrict__ g, const float* __restrict__ bb,
          __nv_bfloat16* __restrict__ out) {
    constexpr int NCH = CIN / 64;
    constexpr int KCP = 144;                 // 128B chunk + 16B pad
    constexpr int PXT = TY * TX;
    constexpr int SIN_PIX = NB * (TY + 2) * (TX + 2);
    constexpr int NI = TOC / 8;              // acc col-tiles
    constexpr int NP = TOC / 16;             // B ldsm per k-step
    constexpr int NG = (9 + WG - 1) / WG;    // weight groups

    extern __shared__ char smem[];
    char* s_in = smem;                       // SIN_PIX * KCP
    char* s_w  = smem + SIN_PIX * KCP;       // WG * TOC * KCP

    const int tid  = threadIdx.x;
    const int warp = tid >> 5, lane = tid & 31;
    const int oc0  = blockIdx.x * TOC;
    const int ty0  = (blockIdx.y / (W / TX)) * TY;
    const int tx0  = (blockIdx.y % (W / TX)) * TX;
    const int n0   = blockIdx.z * NB;
    const char* inb = (const char*)in;
    const char* wqb = (const char*)wq;

    float acc[2][NI][4];
#pragma unroll
    for (int mi = 0; mi < 2; mi++)
#pragma unroll
        for (int ni = 0; ni < NI; ni++)
#pragma unroll
            for (int j = 0; j < 4; j++) acc[mi][ni][j] = 0.0f;

    unsigned Abase[2];
#pragma unroll
    for (int mi = 0; mi < 2; mi++) {
        int row_local = ((lane >> 3) & 1) * 8 + (lane & 7);
        int p = warp * 32 + mi * 16 + row_local;
        int nn = p / PXT, rem = p % PXT;
        int py = rem / TX, px = rem % TX;
        Abase[mi] = smem_u32(s_in) + ((nn * (TY + 2) + py) * (TX + 2) + px) * KCP
                    + (lane >> 4) * 16;
    }
    const unsigned Bbase = smem_u32(s_w) + ((lane & 7) + (lane >> 4) * 8) * KCP
                           + ((lane >> 3) & 1) * 16;

    for (int ch = 0; ch < NCH; ch++) {
#pragma unroll
        for (int gg = 0; gg < NG; gg++) {
            const int k0 = gg * WG;
            const int kN = (9 - k0 < WG) ? (9 - k0) : WG;
            if (gg == 0) {
                for (int u = tid; u < SIN_PIX * 8; u += 256) {
                    int j   = u & 7;
                    int pix = u >> 3;
                    int xx  = pix % (TX + 2);
                    int yy  = (pix / (TX + 2)) % (TY + 2);
                    int nn  = pix / ((TX + 2) * (TY + 2));
                    int gy = ty0 + yy - 1, gx = tx0 + xx - 1;
                    bool ok = (unsigned)gy < (unsigned)H && (unsigned)gx < (unsigned)W;
                    const char* src = ok
                        ? inb + ((((size_t)(n0 + nn) * H + gy) * W + gx) * CIN + ch * 64 + j * 8) * 2
                        : inb;
                    cp16(smem_u32(s_in + pix * KCP + j * 16), src, ok ? 16 : 0);
                }
            }
            for (int u = tid; u < kN * TOC * 8; u += 256) {
                int j   = u & 7;
                int r   = (u >> 3) % TOC;
                int kl  = u / (TOC * 8);
                const char* src = wqb +
                    (((size_t)((k0 + kl) * NCH + ch) * COUT + oc0 + r) * 64 + j * 8) * 2;
                cp16(smem_u32(s_w + (kl * TOC + r) * KCP + j * 16), src, 16);
            }
            cp_commit_wait();
            __syncthreads();

#pragma unroll
            for (int kl = 0; kl < WG; kl++) {
                if (kl >= kN) break;
                const int kpos = k0 + kl;
                const int off0 = ((kpos / 3) * (TX + 2) + (kpos % 3)) * KCP;
#pragma unroll
                for (int ks = 0; ks < 4; ks++) {
                    const int off = off0 + ks * 32;
                    unsigned a0[4], a1[4];
                    ldsm4(a0, Abase[0] + off);
                    ldsm4(a1, Abase[1] + off);
#pragma unroll
                    for (int np = 0; np < NP; np++) {
                        unsigned b[4];
                        ldsm4(b, Bbase + (kl * TOC + np * 16) * KCP + ks * 32);
                        mma_bf16(acc[0][2 * np],     a0, b[0], b[1]);
                        mma_bf16(acc[0][2 * np + 1], a0, b[2], b[3]);
                        mma_bf16(acc[1][2 * np],     a1, b[0], b[1]);
                        mma_bf16(acc[1][2 * np + 1], a1, b[2], b[3]);
                    }
                }
            }
            __syncthreads();
        }
    }

    if (POOL == 1) {
        const int q = lane >> 2;
#pragma unroll
        for (int half = 0; half < 2; half++) {
            const int px = half * 8 + q;
#pragma unroll
            for (int ni = 0; ni < NI; ni++) {
                int col = ni * 8 + (lane & 3) * 2;
                float m[2];
#pragma unroll
                for (int l = 0; l < 2; l++) {
                    float lv2[2];
#pragma unroll
                    for (int mi = 0; mi < 2; mi++) {
                        float y = acc[mi][ni][half * 2 + l] / 49.0f;
                        float p = y * g[oc0 + col + l] + bb[oc0 + col + l];
                        p = fminf(fmaxf(p, -1.0f), 1.0f);
                        lv2[mi] = fmaxf(rintf(p * 7.0f), 0.0f);
                    }
                    m[l] = fmaxf(lv2[0], lv2[1]);
                    m[l] = fmaxf(m[l], __shfl_xor_sync(0xFFFFFFFFu, m[l], 4));
                }
                if (!(q & 1)) {
                    int oy = ty0 / 2 + warp;
                    int ox = tx0 / 2 + px / 2;
                    size_t ob = (((size_t)n0 * (H / 2) + oy) * (W / 2) + ox) * COUT + oc0 + col;
                    *(unsigned*)((char*)out + ob * 2) = pack_bf16x2(m[0], m[1]);
                }
            }
        }
    } else if (POOL == 2) {
        const int q = lane >> 2;
#pragma unroll
        for (int mi = 0; mi < 2; mi++) {
            int rbase = warp * 32 + mi * 16;
            int nn = rbase / PXT;
            int py = (rbase % PXT) / TX;
            int oy = py >> 1;
#pragma unroll
            for (int ni = 0; ni < NI; ni++) {
                int col = ni * 8 + (lane & 3) * 2;
                float m[2];
#pragma unroll
                for (int l = 0; l < 2; l++) {
                    float lv2[2];
#pragma unroll
                    for (int half = 0; half < 2; half++) {
                        float y = acc[mi][ni][half * 2 + l] / 49.0f;
                        float p = y * g[oc0 + col + l] + bb[oc0 + col + l];
                        p = fminf(fmaxf(p, -1.0f), 1.0f);
                        lv2[half] = fmaxf(rintf(p * 7.0f), 0.0f);
                    }
                    m[l] = fmaxf(lv2[0], lv2[1]);
                    m[l] = fmaxf(m[l], __shfl_xor_sync(0xFFFFFFFFu, m[l], 4));
                }
                unsigned hw = (unsigned)(int)m[0] | ((unsigned)(int)m[1] << 8);
                unsigned other = __shfl_xor_sync(0xFFFFFFFFu, hw, 1);
                if ((lane & 5) == 0) {
                    int c4 = (oc0 >> 2) + 2 * ni + ((lane & 3) >> 1);
                    int ox = q >> 1;
                    int pxi = oy * 4 + ox;
                    ((unsigned*)out)[(size_t)(n0 + nn) * 1024 + pxi * 64 + c4] =
                        hw | (other << 16);
                }
            }
        }
    } else {
#pragma unroll
        for (int mi = 0; mi < 2; mi++) {
#pragma unroll
            for (int half = 0; half < 2; half++) {
                int row = warp * 32 + mi * 16 + (lane >> 2) + half * 8;
                int nn = row / PXT, rem = row % PXT;
                int py = rem / TX, px = rem % TX;
                size_t ob = (((size_t)(n0 + nn) * H + ty0 + py) * W + tx0 + px) * COUT + oc0;
#pragma unroll
                for (int ni = 0; ni < NI; ni++) {
                    int col = ni * 8 + (lane & 3) * 2;
                    float lv[2];
#pragma unroll
                    for (int l = 0; l < 2; l++) {
                        float y = acc[mi][ni][half * 2 + l] / 49.0f;
                        float p = y * g[oc0 + col + l] + bb[oc0 + col + l];
                        p = fminf(fmaxf(p, -1.0f), 1.0f);
                        lv[l] = fmaxf(rintf(p * 7.0f), 0.0f);
                    }
                    *(unsigned*)((char*)out + (ob + col) * 2) = pack_bf16x2(lv[0], lv[1]);
                }
            }
        }
    }
}

// ---------------- FC ----------------
__global__ void fc1_kernel(const int* __restrict__ h, const int* __restrict__ w,
                           const float* __restrict__ g, const float* __restrict__ b,
                           unsigned char* __restrict__ out) {
    __shared__ int sa[16][17];
    __shared__ int sw[16][17];
    const int tx = threadIdx.x, ty = threadIdx.y;
    const int n = blockIdx.y * 16 + ty;
    const int o = blockIdx.x * 16 + tx;
    int acc = 0;
    for (int m0 = 0; m0 < 1024; m0 += 16) {
        sa[ty][tx] = h[(blockIdx.y * 16 + ty) * 1024 + m0 + tx];
        sw[ty][tx] = w[(blockIdx.x * 16 + ty) * 1024 + m0 + tx];
        __syncthreads();
#pragma unroll
        for (int mm = 0; mm < 16; mm++) acc = __dp4a(sa[ty][mm], sw[tx][mm], acc);
        __syncthreads();
    }
    float y = (float)acc / 49.0f;
    float p = y * g[o] + b[o];
    p = fminf(fmaxf(p, -1.0f), 1.0f);
    int lev = max((int)rintf(p * 7.0f), 0);
    out[n * 512 + o] = (unsigned char)lev;
}
__global__ void fc2_kernel(const unsigned char* __restrict__ h,
                           const signed char* __restrict__ w,
                           const float* __restrict__ g, const float* __restrict__ b,
                           float* __restrict__ out) {
    const int n = blockIdx.x;
    const int lane = threadIdx.x;
    for (int o = 0; o < 10; o++) {
        int acc = 0;
        for (int k = lane; k < 512; k += 32)
            acc += (int)h[n * 512 + k] * (int)w[o * 512 + k];
#pragma unroll
        for (int off = 16; off > 0; off >>= 1)
            acc += __shfl_xor_sync(0xFFFFFFFFu, acc, off);
        if (lane == 0) {
            float y = (float)acc / 49.0f;
            float p = y * g[o] + b[o];
            p = fminf(fmaxf(p, -1.0f), 1.0f);
            out[n * 10 + o] = (float)((int)rintf(p * 7.0f)) / 7.0f;
        }
    }
}

// ---------------- launch ----------------
extern "C" void kernel_launch(void* const* d_in, const int* in_sizes, int n_in,
                              void* d_out, int out_size) {
    const float* x = (const float*)d_in[0];
    const float *w1 = (const float*)d_in[1], *g1 = (const float*)d_in[2], *b1 = (const float*)d_in[3];
    const float *w2 = (const float*)d_in[4], *g2 = (const float*)d_in[5], *b2 = (const float*)d_in[6];
    const float *w3 = (const float*)d_in[7], *g3 = (const float*)d_in[8], *b3 = (const float*)d_in[9];
    const float *w4 = (const float*)d_in[10], *g4 = (const float*)d_in[11], *b4 = (const float*)d_in[12];
    const float *w5 = (const float*)d_in[13], *g5 = (const float*)d_in[14], *b5 = (const float*)d_in[15];
    const float *w6 = (const float*)d_in[16], *g6 = (const float*)d_in[17], *b6 = (const float*)d_in[18];
    const float *wf1 = (const float*)d_in[19], *gf1 = (const float*)d_in[20], *bf1 = (const float*)d_in[21];
    const float *wf2 = (const float*)d_in[22], *gf2 = (const float*)d_in[23], *bf2 = (const float*)d_in[24];

    void *bufA, *bufB, *qw1, *w2p, *w3p, *w4p, *w5p, *w6p, *wf1p, *wf2p, *fc1o;
    cudaGetSymbolAddress(&bufA, g_bufA);
    cudaGetSymbolAddress(&bufB, g_bufB);
    cudaGetSymbolAddress(&qw1, g_qw1);
    cudaGetSymbolAddress(&w2p, g_wb2);
    cudaGetSymbolAddress(&w3p, g_wb3);
    cudaGetSymbolAddress(&w4p, g_wb4);
    cudaGetSymbolAddress(&w5p, g_wb5);
    cudaGetSymbolAddress(&w6p, g_wb6);
    cudaGetSymbolAddress(&wf1p, g_wf1);
    cudaGetSymbolAddress(&wf2p, g_wf2);
    cudaGetSymbolAddress(&fc1o, g_fc1);

    auto k2 = conv_hmma<32, 32, 16, 16, 1, 64, 64, 1, 32, 3, 5>;     // pool -> 16x16
    auto k3 = conv_hmma<16, 16, 16, 16, 1, 64, 128, 0, 32, 3, 5>;
    auto k4 = conv_hmma<16, 16, 16, 16, 1, 128, 128, 1, 32, 3, 5>;   // pool -> 8x8
    auto k5 = conv_hmma<8, 8, 8, 8, 4, 128, 256, 0, 32, 3, 3>;
    auto k6 = conv_hmma<8, 8, 8, 8, 4, 256, 256, 2, 32, 3, 3>;       // pool+int8 pack
    const int sm32 = (1 * 18 * 18) * 144 + 5 * 32 * 144;   // 69696
    const int sm56 = (4 * 10 * 10) * 144 + 3 * 32 * 144;   // 57600+13824 = 71424
    cudaFuncSetAttribute(k2, cudaFuncAttributeMaxDynamicSharedMemorySize, sm32);
    cudaFuncSetAttribute(k3, cudaFuncAttributeMaxDynamicSharedMemorySize, sm32);
    cudaFuncSetAttribute(k4, cudaFuncAttributeMaxDynamicSharedMemorySize, sm32);
    cudaFuncSetAttribute(k5, cudaFuncAttributeMaxDynamicSharedMemorySize, sm56);
    cudaFuncSetAttribute(k6, cudaFuncAttributeMaxDynamicSharedMemorySize, sm56);

    prep_all<<<(1673920 + 255) / 256, 256>>>(
        w1, w2, w3, w4, w5, w6, wf1, wf2,
        (float*)qw1, (__nv_bfloat16*)w2p, (__nv_bfloat16*)w3p, (__nv_bfloat16*)w4p,
        (__nv_bfloat16*)w5p, (__nv_bfloat16*)w6p, (int*)wf1p, (signed char*)wf2p);

    conv1_kernel<<<dim3(4, 512), 1024>>>(x, (const float*)qw1, g1, b1, (__nv_bfloat16*)bufA);

    // L2+pool: 64->64 @32 -> 16x16, A->B
    k2<<<dim3(2, 4, 512), 256, sm32>>>((const __nv_bfloat16*)bufA, (const __nv_bfloat16*)w2p,
                                       g2, b2, (__nv_bfloat16*)bufB);
    // L3: 64->128 @16, B->A
    k3<<<dim3(4, 1, 512), 256, sm32>>>((const __nv_bfloat16*)bufB, (const __nv_bfloat16*)w3p,
                                       g3, b3, (__nv_bfloat16*)bufA);
    // L4+pool: 128->128 @16 -> 8x8, A->B
    k4<<<dim3(4, 1, 512), 256, sm32>>>((const __nv_bfloat16*)bufA, (const __nv_bfloat16*)w4p,
                                       g4, b4, (__nv_bfloat16*)bufB);
    // L5: 128->256 @8, B->A
    k5<<<dim3(8, 1, 128), 256, sm56>>>((const __nv_bfloat16*)bufB, (const __nv_bfloat16*)w5p,
                                       g5, b5, (__nv_bfloat16*)bufA);
    // L6+pool+pack: 256->256 @8 -> 4x4 packed int8, A->B
    k6<<<dim3(8, 1, 128), 256, sm56>>>((const __nv_bfloat16*)bufA, (const __nv_bfloat16*)w6p,
                                       g6, b6, (__nv_bfloat16*)bufB);

    fc1_kernel<<<dim3(32, 32), dim3(16, 16)>>>((const int*)bufB, (const int*)wf1p, gf1, bf1,
                                               (unsigned char*)fc1o);
    fc2_kernel<<<512, 32>>>((const unsigned char*)fc1o, (const signed char*)wf2p, gf2, bf2,
                            (float*)d_out);
}

// round 16
// speedup vs baseline: 1.0959x; 1.0156x over previous
#include <cuda_runtime.h>
#include <cuda_bf16.h>
#include <cstdint>

// ============================================================================
// IntegerCifar10Net R16: R15 + L2/L3/L4 at occupancy 4 (64-reg cap, 2-tap
// weight groups, 55.9KB smem/CTA). L5/L6 stay occ-3. Exact integer math.
// ============================================================================

__device__ __forceinline__ int qlev(float w) {
    w = fminf(fmaxf(w, -1.0f), 1.0f);
    return (int)rintf(w * 7.0f);
}
__device__ __forceinline__ unsigned pack_bf16x2(float lo, float hi) {
    unsigned r;
    asm("cvt.rn.bf16x2.f32 %0, %1, %2;" : "=r"(r) : "f"(hi), "f"(lo));
    return r;
}
__device__ __forceinline__ unsigned smem_u32(const void* p) {
    return (unsigned)__cvta_generic_to_shared(p);
}
__device__ __forceinline__ void cp16(unsigned dst, const void* src, int szvalid) {
    asm volatile("cp.async.cg.shared.global [%0], [%1], 16, %2;"
                 :: "r"(dst), "l"(src), "r"(szvalid) : "memory");
}
__device__ __forceinline__ void cp_commit_wait() {
    asm volatile("cp.async.commit_group;" ::: "memory");
    asm volatile("cp.async.wait_group 0;" ::: "memory");
}
__device__ __forceinline__ void ldsm4(unsigned* r, unsigned addr) {
    asm volatile("ldmatrix.sync.aligned.m8n8.x4.shared.b16 {%0,%1,%2,%3}, [%4];"
                 : "=r"(r[0]), "=r"(r[1]), "=r"(r[2]), "=r"(r[3]) : "r"(addr));
}

// ---------------- scratch ----------------
__device__ __nv_bfloat16 g_bufA[512 * 32 * 32 * 64];
__device__ __nv_bfloat16 g_bufB[512 * 32 * 32 * 64];
__device__ float         g_qw1[64 * 3 * 9];
__device__ __nv_bfloat16 g_wb2[9 * 1 * 64 * 64];
__device__ __nv_bfloat16 g_wb3[9 * 1 * 128 * 64];
__device__ __nv_bfloat16 g_wb4[9 * 2 * 128 * 64];
__device__ __nv_bfloat16 g_wb5[9 * 2 * 256 * 64];
__device__ __nv_bfloat16 g_wb6[9 * 4 * 256 * 64];
__device__ int           g_wf1[512 * 1024];
__device__ signed char   g_wf2[10 * 512];
__device__ unsigned char g_fc1[512 * 512];

// ---------------- fused weight prep ----------------
__device__ __forceinline__ void pack_one_convw(const float* w, __nv_bfloat16* out,
                                               int COUT, int CIN, int idx) {
    int NCH = CIN / 64;
    int j = idx % 64;
    int t = idx / 64;
    int oc = t % COUT; t /= COUT;
    int ch = t % NCH;
    int kpos = t / NCH;
    out[idx] = __float2bfloat16((float)qlev(w[(oc * CIN + ch * 64 + j) * 9 + kpos]));
}

__global__ void prep_all(const float* w1, const float* w2, const float* w3,
                         const float* w4, const float* w5, const float* w6,
                         const float* wf1, const float* wf2,
                         float* qw1, __nv_bfloat16* o2, __nv_bfloat16* o3,
                         __nv_bfloat16* o4, __nv_bfloat16* o5, __nv_bfloat16* o6,
                         int* of1, signed char* of2) {
    int idx = blockIdx.x * blockDim.x + threadIdx.x;
    const int S0 = 1728, S1 = 36864, S2 = 73728, S3 = 147456,
              S4 = 294912, S5 = 589824, S6 = 524288, S7 = 5120;
    if (idx < S0) { qw1[idx] = (float)qlev(w1[idx]) / 7.0f; return; }
    idx -= S0;
    if (idx < S1) { pack_one_convw(w2, o2, 64, 64, idx); return; }
    idx -= S1;
    if (idx < S2) { pack_one_convw(w3, o3, 128, 64, idx); return; }
    idx -= S2;
    if (idx < S3) { pack_one_convw(w4, o4, 128, 128, idx); return; }
    idx -= S3;
    if (idx < S4) { pack_one_convw(w5, o5, 256, 128, idx); return; }
    idx -= S4;
    if (idx < S5) { pack_one_convw(w6, o6, 256, 256, idx); return; }
    idx -= S5;
    if (idx < S6) {
        int wi = idx % 1024, o = idx / 1024;
        int px = wi / 64, c4 = wi % 64;
        unsigned word = 0;
#pragma unroll
        for (int l = 0; l < 4; l++) {
            int k = (4 * c4 + l) * 16 + px;
            word |= (unsigned)(qlev(wf1[o * 4096 + k]) & 0xFF) << (8 * l);
        }
        of1[idx] = (int)word;
        return;
    }
    idx -= S6;
    if (idx < S7) of2[idx] = (signed char)qlev(wf2[idx]);
}

// ---------------- conv1: fp32 NCHW -> bf16 NHWC levels ----------------
__global__ void __launch_bounds__(1024)
conv1_kernel(const float* __restrict__ x, const float* __restrict__ qw,
             const float* __restrict__ g, const float* __restrict__ b,
             __nv_bfloat16* __restrict__ out) {
    __shared__ float s_in[3][34][34];
    __shared__ float s_w[16][27];
    const int tid = threadIdx.x;
    const int oy = tid / 32, ox = tid % 32;
    const int n = blockIdx.y;
    const int oc0 = blockIdx.x * 16;
    for (int i = tid; i < 3 * 34 * 34; i += 1024) {
        int t = i;
        int xx = t % 34; t /= 34;
        int yy = t % 34; t /= 34;
        int c = t;
        int yi = yy - 1, xi = xx - 1;
        float v = 0.0f;
        if ((unsigned)yi < 32u && (unsigned)xi < 32u)
            v = x[((n * 3 + c) * 32 + yi) * 32 + xi];
        s_in[c][yy][xx] = v;
    }
    for (int i = tid; i < 16 * 27; i += 1024)
        s_w[i / 27][i % 27] = qw[(oc0 + i / 27) * 27 + i % 27];
    __syncthreads();
    float acc[16];
#pragma unroll
    for (int o = 0; o < 16; o++) acc[o] = 0.0f;
#pragma unroll
    for (int c = 0; c < 3; c++) {
        float wv[9];
#pragma unroll
        for (int ky = 0; ky < 3; ky++)
#pragma unroll
            for (int kx = 0; kx < 3; kx++)
                wv[ky * 3 + kx] = s_in[c][oy + ky][ox + kx];
#pragma unroll
        for (int o = 0; o < 16; o++) {
            float a = acc[o];
#pragma unroll
            for (int k = 0; k < 9; k++) a = fmaf(wv[k], s_w[o][c * 9 + k], a);
            acc[o] = a;
        }
    }
    unsigned* ob = (unsigned*)(out + ((size_t)(n * 1024) + oy * 32 + ox) * 64 + oc0);
#pragma unroll
    for (int j = 0; j < 8; j++) {
        float lv[2];
#pragma unroll
        for (int l = 0; l < 2; l++) {
            int o = j * 2 + l;
            float p = acc[o] * g[oc0 + o] + b[oc0 + o];
            p = fminf(fmaxf(p, -1.0f), 1.0f);
            lv[l] = fmaxf(rintf(p * 7.0f), 0.0f);
        }
        ob[j] = pack_bf16x2(lv[0], lv[1]);
    }
}

// ---------------- bf16 HMMA conv ----------------
__device__ __forceinline__ void mma_bf16(float* d, const unsigned* a, unsigned b0, unsigned b1) {
    asm volatile(
        "mma.sync.aligned.m16n8k16.row.col.f32.bf16.bf16.f32 "
        "{%0,%1,%2,%3},{%4,%5,%6,%7},{%8,%9},{%0,%1,%2,%3};"
        : "+f"(d[0]), "+f"(d[1]), "+f"(d[2]), "+f"(d[3])
        : "r"(a[0]), "r"(a[1]), "r"(a[2]), "r"(a[3]), "r"(b0), "r"(b1));
}

// act [n][H][W][CIN] bf16 ; weight [kpos][ch][oc][64] bf16
// Warp tile M=32 px, N=TOC oc. POOL: 0=none, 1=pooled bf16 out (TY=TX=16,NB=1),
// 2=pooled packed-int8 out for FC1 (TY=TX=8, NB=4).
// WG = taps per weight-stage group.
template <int H, int W, int TY, int TX, int NB, int CIN, int COUT, int POOL,
          int TOC, int MINB, int WG>
__global__ void __launch_bounds__(256, MINB)
conv_hmma(const __nv_bfloat16* __restrict__ in, const __nv_bfloat16* __restrict__ wq,
          const float* __restrict__ g, const float* __restrict__ bb,
          __nv_bfloat16* __restrict__ out) {
    constexpr int NCH = CIN / 64;
    constexpr int KCP = 144;                 // 128B chunk + 16B pad
    constexpr int PXT = TY * TX;
    constexpr int SIN_PIX = NB * (TY + 2) * (TX + 2);
    constexpr int NI = TOC / 8;              // acc col-tiles
    constexpr int NP = TOC / 16;             // B ldsm per k-step
    constexpr int NG = (9 + WG - 1) / WG;    // weight groups

    extern __shared__ char smem[];
    char* s_in = smem;                       // SIN_PIX * KCP
    char* s_w  = smem + SIN_PIX * KCP;       // WG * TOC * KCP

    const int tid  = threadIdx.x;
    const int warp = tid >> 5, lane = tid & 31;
    const int oc0  = blockIdx.x * TOC;
    const int ty0  = (blockIdx.y / (W / TX)) * TY;
    const int tx0  = (blockIdx.y % (W / TX)) * TX;
    const int n0   = blockIdx.z * NB;
    const char* inb = (const char*)in;
    const char* wqb = (const char*)wq;

    float acc[2][NI][4];
#pragma unroll
    for (int mi = 0; mi < 2; mi++)
#pragma unroll
        for (int ni = 0; ni < NI; ni++)
#pragma unroll
            for (int j = 0; j < 4; j++) acc[mi][ni][j] = 0.0f;

    unsigned Abase[2];
#pragma unroll
    for (int mi = 0; mi < 2; mi++) {
        int row_local = ((lane >> 3) & 1) * 8 + (lane & 7);
        int p = warp * 32 + mi * 16 + row_local;
        int nn = p / PXT, rem = p % PXT;
        int py = rem / TX, px = rem % TX;
        Abase[mi] = smem_u32(s_in) + ((nn * (TY + 2) + py) * (TX + 2) + px) * KCP
                    + (lane >> 4) * 16;
    }
    const unsigned Bbase = smem_u32(s_w) + ((lane & 7) + (lane >> 4) * 8) * KCP
                           + ((lane >> 3) & 1) * 16;

    for (int ch = 0; ch < NCH; ch++) {
#pragma unroll
        for (int gg = 0; gg < NG; gg++) {
            const int k0 = gg * WG;
            const int kN = (9 - k0 < WG) ? (9 - k0) : WG;
            if (gg == 0) {
                for (int u = tid; u < SIN_PIX * 8; u += 256) {
                    int j   = u & 7;
                    int pix = u >> 3;
                    int xx  = pix % (TX + 2);
                    int yy  = (pix / (TX + 2)) % (TY + 2);
                    int nn  = pix / ((TX + 2) * (TY + 2));
                    int gy = ty0 + yy - 1, gx = tx0 + xx - 1;
                    bool ok = (unsigned)gy < (unsigned)H && (unsigned)gx < (unsigned)W;
                    const char* src = ok
                        ? inb + ((((size_t)(n0 + nn) * H + gy) * W + gx) * CIN + ch * 64 + j * 8) * 2
                        : inb;
                    cp16(smem_u32(s_in + pix * KCP + j * 16), src, ok ? 16 : 0);
                }
            }
            for (int u = tid; u < kN * TOC * 8; u += 256) {
                int j   = u & 7;
                int r   = (u >> 3) % TOC;
                int kl  = u / (TOC * 8);
                const char* src = wqb +
                    (((size_t)((k0 + kl) * NCH + ch) * COUT + oc0 + r) * 64 + j * 8) * 2;
                cp16(smem_u32(s_w + (kl * TOC + r) * KCP + j * 16), src, 16);
            }
            cp_commit_wait();
            __syncthreads();

#pragma unroll
            for (int kl = 0; kl < WG; kl++) {
                if (kl >= kN) break;
                const int kpos = k0 + kl;
                const int off0 = ((kpos / 3) * (TX + 2) + (kpos % 3)) * KCP;
#pragma unroll
                for (int ks = 0; ks < 4; ks++) {
                    const int off = off0 + ks * 32;
                    unsigned a0[4], a1[4];
                    ldsm4(a0, Abase[0] + off);
                    ldsm4(a1, Abase[1] + off);
#pragma unroll
                    for (int np = 0; np < NP; np++) {
                        unsigned b[4];
                        ldsm4(b, Bbase + (kl * TOC + np * 16) * KCP + ks * 32);
                        mma_bf16(acc[0][2 * np],     a0, b[0], b[1]);
                        mma_bf16(acc[0][2 * np + 1], a0, b[2], b[3]);
                        mma_bf16(acc[1][2 * np],     a1, b[0], b[1]);
                        mma_bf16(acc[1][2 * np + 1], a1, b[2], b[3]);
                    }
                }
            }
            __syncthreads();
        }
    }

    if (POOL == 1) {
        const int q = lane >> 2;
#pragma unroll
        for (int half = 0; half < 2; half++) {
            const int px = half * 8 + q;
#pragma unroll
            for (int ni = 0; ni < NI; ni++) {
                int col = ni * 8 + (lane & 3) * 2;
                float m[2];
#pragma unroll
                for (int l = 0; l < 2; l++) {
                    float lv2[2];
#pragma unroll
                    for (int mi = 0; mi < 2; mi++) {
                        float y = acc[mi][ni][half * 2 + l] / 49.0f;
                        float p = y * g[oc0 + col + l] + bb[oc0 + col + l];
                        p = fminf(fmaxf(p, -1.0f), 1.0f);
                        lv2[mi] = fmaxf(rintf(p * 7.0f), 0.0f);
                    }
                    m[l] = fmaxf(lv2[0], lv2[1]);
                    m[l] = fmaxf(m[l], __shfl_xor_sync(0xFFFFFFFFu, m[l], 4));
                }
                if (!(q & 1)) {
                    int oy = ty0 / 2 + warp;
                    int ox = tx0 / 2 + px / 2;
                    size_t ob = (((size_t)n0 * (H / 2) + oy) * (W / 2) + ox) * COUT + oc0 + col;
                    *(unsigned*)((char*)out + ob * 2) = pack_bf16x2(m[0], m[1]);
                }
            }
        }
    } else if (POOL == 2) {
        const int q = lane >> 2;
#pragma unroll
        for (int mi = 0; mi < 2; mi++) {
            int rbase = warp * 32 + mi * 16;
            int nn = rbase / PXT;
            int py = (rbase % PXT) / TX;
            int oy = py >> 1;
#pragma unroll
            for (int ni = 0; ni < NI; ni++) {
                int col = ni * 8 + (lane & 3) * 2;
                float m[2];
#pragma unroll
                for (int l = 0; l < 2; l++) {
                    float lv2[2];
#pragma unroll
                    for (int half = 0; half < 2; half++) {
                        float y = acc[mi][ni][half * 2 + l] / 49.0f;
                        float p = y * g[oc0 + col + l] + bb[oc0 + col + l];
                        p = fminf(fmaxf(p, -1.0f), 1.0f);
                        lv2[half] = fmaxf(rintf(p * 7.0f), 0.0f);
                    }
                    m[l] = fmaxf(lv2[0], lv2[1]);
                    m[l] = fmaxf(m[l], __shfl_xor_sync(0xFFFFFFFFu, m[l], 4));
                }
                unsigned hw = (unsigned)(int)m[0] | ((unsigned)(int)m[1] << 8);
                unsigned other = __shfl_xor_sync(0xFFFFFFFFu, hw, 1);
                if ((lane & 5) == 0) {
                    int c4 = (oc0 >> 2) + 2 * ni + ((lane & 3) >> 1);
                    int ox = q >> 1;
                    int pxi = oy * 4 + ox;
                    ((unsigned*)out)[(size_t)(n0 + nn) * 1024 + pxi * 64 + c4] =
                        hw | (other << 16);
                }
            }
        }
    } else {
#pragma unroll
        for (int mi = 0; mi < 2; mi++) {
#pragma unroll
            for (int half = 0; half < 2; half++) {
                int row = warp * 32 + mi * 16 + (lane >> 2) + half * 8;
                int nn = row / PXT, rem = row % PXT;
                int py = rem / TX, px = rem % TX;
                size_t ob = (((size_t)(n0 + nn) * H + ty0 + py) * W + tx0 + px) * COUT + oc0;
#pragma unroll
                for (int ni = 0; ni < NI; ni++) {
                    int col = ni * 8 + (lane & 3) * 2;
                    float lv[2];
#pragma unroll
                    for (int l = 0; l < 2; l++) {
                        float y = acc[mi][ni][half * 2 + l] / 49.0f;
                        float p = y * g[oc0 + col + l] + bb[oc0 + col + l];
                        p = fminf(fmaxf(p, -1.0f), 1.0f);
                        lv[l] = fmaxf(rintf(p * 7.0f), 0.0f);
                    }
                    *(unsigned*)((char*)out + (ob + col) * 2) = pack_bf16x2(lv[0], lv[1]);
                }
            }
        }
    }
}

// ---------------- FC ----------------
__global__ void fc1_kernel(const int* __restrict__ h, const int* __restrict__ w,
                           const float* __restrict__ g, const float* __restrict__ b,
                           unsigned char* __restrict__ out) {
    __shared__ int sa[16][17];
    __shared__ int sw[16][17];
    const int tx = threadIdx.x, ty = threadIdx.y;
    const int n = blockIdx.y * 16 + ty;
    const int o = blockIdx.x * 16 + tx;
    int acc = 0;
    for (int m0 = 0; m0 < 1024; m0 += 16) {
        sa[ty][tx] = h[(blockIdx.y * 16 + ty) * 1024 + m0 + tx];
        sw[ty][tx] = w[(blockIdx.x * 16 + ty) * 1024 + m0 + tx];
        __syncthreads();
#pragma unroll
        for (int mm = 0; mm < 16; mm++) acc = __dp4a(sa[ty][mm], sw[tx][mm], acc);
        __syncthreads();
    }
    float y = (float)acc / 49.0f;
    float p = y * g[o] + b[o];
    p = fminf(fmaxf(p, -1.0f), 1.0f);
    int lev = max((int)rintf(p * 7.0f), 0);
    out[n * 512 + o] = (unsigned char)lev;
}
__global__ void fc2_kernel(const unsigned char* __restrict__ h,
                           const signed char* __restrict__ w,
                           const float* __restrict__ g, const float* __restrict__ b,
                           float* __restrict__ out) {
    const int n = blockIdx.x;
    const int lane = threadIdx.x;
    for (int o = 0; o < 10; o++) {
        int acc = 0;
        for (int k = lane; k < 512; k += 32)
            acc += (int)h[n * 512 + k] * (int)w[o * 512 + k];
#pragma unroll
        for (int off = 16; off > 0; off >>= 1)
            acc += __shfl_xor_sync(0xFFFFFFFFu, acc, off);
        if (lane == 0) {
            float y = (float)acc / 49.0f;
            float p = y * g[o] + b[o];
            p = fminf(fmaxf(p, -1.0f), 1.0f);
            out[n * 10 + o] = (float)((int)rintf(p * 7.0f)) / 7.0f;
        }
    }
}

// ---------------- launch ----------------
extern "C" void kernel_launch(void* const* d_in, const int* in_sizes, int n_in,
                              void* d_out, int out_size) {
    const float* x = (const float*)d_in[0];
    const float *w1 = (const float*)d_in[1], *g1 = (const float*)d_in[2], *b1 = (const float*)d_in[3];
    const float *w2 = (const float*)d_in[4], *g2 = (const float*)d_in[5], *b2 = (const float*)d_in[6];
    const float *w3 = (const float*)d_in[7], *g3 = (const float*)d_in[8], *b3 = (const float*)d_in[9];
    const float *w4 = (const float*)d_in[10], *g4 = (const float*)d_in[11], *b4 = (const float*)d_in[12];
    const float *w5 = (const float*)d_in[13], *g5 = (const float*)d_in[14], *b5 = (const float*)d_in[15];
    const float *w6 = (const float*)d_in[16], *g6 = (const float*)d_in[17], *b6 = (const float*)d_in[18];
    const float *wf1 = (const float*)d_in[19], *gf1 = (const float*)d_in[20], *bf1 = (const float*)d_in[21];
    const float *wf2 = (const float*)d_in[22], *gf2 = (const float*)d_in[23], *bf2 = (const float*)d_in[24];

    void *bufA, *bufB, *qw1, *w2p, *w3p, *w4p, *w5p, *w6p, *wf1p, *wf2p, *fc1o;
    cudaGetSymbolAddress(&bufA, g_bufA);
    cudaGetSymbolAddress(&bufB, g_bufB);
    cudaGetSymbolAddress(&qw1, g_qw1);
    cudaGetSymbolAddress(&w2p, g_wb2);
    cudaGetSymbolAddress(&w3p, g_wb3);
    cudaGetSymbolAddress(&w4p, g_wb4);
    cudaGetSymbolAddress(&w5p, g_wb5);
    cudaGetSymbolAddress(&w6p, g_wb6);
    cudaGetSymbolAddress(&wf1p, g_wf1);
    cudaGetSymbolAddress(&wf2p, g_wf2);
    cudaGetSymbolAddress(&fc1o, g_fc1);

    auto k2 = conv_hmma<32, 32, 16, 16, 1, 64, 64, 1, 32, 4, 2>;     // pool -> 16x16
    auto k3 = conv_hmma<16, 16, 16, 16, 1, 64, 128, 0, 32, 4, 2>;
    auto k4 = conv_hmma<16, 16, 16, 16, 1, 128, 128, 1, 32, 4, 2>;   // pool -> 8x8
    auto k5 = conv_hmma<8, 8, 8, 8, 4, 128, 256, 0, 32, 3, 3>;
    auto k6 = conv_hmma<8, 8, 8, 8, 4, 256, 256, 2, 32, 3, 3>;       // pool+int8 pack
    const int sm234 = (1 * 18 * 18) * 144 + 2 * 32 * 144;  // 46656+9216 = 55872
    const int sm56  = (4 * 10 * 10) * 144 + 3 * 32 * 144;  // 57600+13824 = 71424
    cudaFuncSetAttribute(k2, cudaFuncAttributeMaxDynamicSharedMemorySize, sm234);
    cudaFuncSetAttribute(k3, cudaFuncAttributeMaxDynamicSharedMemorySize, sm234);
    cudaFuncSetAttribute(k4, cudaFuncAttributeMaxDynamicSharedMemorySize, sm234);
    cudaFuncSetAttribute(k5, cudaFuncAttributeMaxDynamicSharedMemorySize, sm56);
    cudaFuncSetAttribute(k6, cudaFuncAttributeMaxDynamicSharedMemorySize, sm56);

    prep_all<<<(1673920 + 255) / 256, 256>>>(
        w1, w2, w3, w4, w5, w6, wf1, wf2,
        (float*)qw1, (__nv_bfloat16*)w2p, (__nv_bfloat16*)w3p, (__nv_bfloat16*)w4p,
        (__nv_bfloat16*)w5p, (__nv_bfloat16*)w6p, (int*)wf1p, (signed char*)wf2p);

    conv1_kernel<<<dim3(4, 512), 1024>>>(x, (const float*)qw1, g1, b1, (__nv_bfloat16*)bufA);

    // L2+pool: 64->64 @32 -> 16x16, A->B
    k2<<<dim3(2, 4, 512), 256, sm234>>>((const __nv_bfloat16*)bufA, (const __nv_bfloat16*)w2p,
                                        g2, b2, (__nv_bfloat16*)bufB);
    // L3: 64->128 @16, B->A
    k3<<<dim3(4, 1, 512), 256, sm234>>>((const __nv_bfloat16*)bufB, (const __nv_bfloat16*)w3p,
                                        g3, b3, (__nv_bfloat16*)bufA);
    // L4+pool: 128->128 @16 -> 8x8, A->B
    k4<<<dim3(4, 1, 512), 256, sm234>>>((const __nv_bfloat16*)bufA, (const __nv_bfloat16*)w4p,
                                        g4, b4, (__nv_bfloat16*)bufB);
    // L5: 128->256 @8, B->A
    k5<<<dim3(8, 1, 128), 256, sm56>>>((const __nv_bfloat16*)bufB, (const __nv_bfloat16*)w5p,
                                       g5, b5, (__nv_bfloat16*)bufA);
    // L6+pool+pack: 256->256 @8 -> 4x4 packed int8, A->B
    k6<<<dim3(8, 1, 128), 256, sm56>>>((const __nv_bfloat16*)bufA, (const __nv_bfloat16*)w6p,
                                       g6, b6, (__nv_bfloat16*)bufB);

    fc1_kernel<<<dim3(32, 32), dim3(16, 16)>>>((const int*)bufB, (const int*)wf1p, gf1, bf1,
                                               (unsigned char*)fc1o);
    fc2_kernel<<<512, 32>>>((const unsigned char*)fc1o, (const signed char*)wf2p, gf2, bf2,
                            (float*)d_out);
}